// round 3
// baseline (speedup 1.0000x reference)
#include <cuda_runtime.h>
#include <math.h>

// Problem constants
#define Bb 128
#define Tt 64
#define Ee 768
#define Hh 768
#define Gg 3072
// L = 2, but layer 0 is dead code (no cross-layer feed; h_last = layer 1 only).

// ---------------- device scratch (no allocations allowed) ----------------
__device__ int   g_len[Bb];
__device__ int   g_actcnt[Tt];
__device__ int   g_act[Tt * Bb];
__device__ int   g_nrows;
__device__ int   g_rows[Bb * Tt];   // packed (b<<6)|t for active (b,t)
__device__ int   g_erow[Bb * Tt];   // embedding row (token id) per active row
__device__ float g_xproj[Tt * Bb * Gg];  // [t][b][g] input projection (layer 1 only)
__device__ float g_h[Bb * Hh];
__device__ float g_c[Bb * Hh];
__device__ float g_gates[Bb * Gg];

__device__ __forceinline__ float sigf(float x) { return 1.0f / (1.0f + expf(-x)); }

// ---------------- K0: dtype detect + length/active-list setup ----------------
// JAX without x64 silently downcasts int64->int32; detect actual width on device:
// if data were int64 (little-endian), every high 32-bit word of message is 0
// (values in [0, 32000)). For int32 data, odd words are real nonzero tokens.
__global__ void k0_setup(const int* __restrict__ msg, const int* __restrict__ mlen) {
    __shared__ int s_flag;
    __shared__ int s_cnt[Tt];
    __shared__ int s_nr;
    int tid = threadIdx.x;
    if (tid == 0) { s_flag = 0; s_nr = 0; }
    if (tid < Tt) s_cnt[tid] = 0;
    __syncthreads();

    int local = 0;
    for (int i = tid; i < (Bb * Tt) / 2; i += 256)
        if (msg[2 * i + 1] != 0) local = 1;
    if (local) atomicOr(&s_flag, 1);
    __syncthreads();
    int is64 = (s_flag == 0);

    if (tid < Bb) {
        int lb = is64 ? mlen[2 * tid] : mlen[tid];
        g_len[tid] = lb;
        for (int t = 0; t < lb; t++) {
            int p = atomicAdd(&s_cnt[t], 1);
            g_act[t * Bb + p] = tid;
            int r = atomicAdd(&s_nr, 1);
            g_rows[r] = (tid << 6) | t;
            int mi = tid * Tt + t;
            g_erow[r] = is64 ? msg[2 * mi] : msg[mi];
        }
    }
    __syncthreads();
    if (tid < Tt) g_actcnt[tid] = s_cnt[tid];
    if (tid == 0) g_nrows = s_nr;
}

// ---------------- K1: input projection GEMM (active rows only) ----------------
// C[row=(b,t), n] = dot(emb_table[token], W_ih[1][n][:]) + b_ih[1][n]
// Tile: 64x64, BK=16, 256 threads, 4x4 per thread.
__global__ void k1_xproj(const float* __restrict__ embt,
                         const float* __restrict__ Wih,
                         const float* __restrict__ bih) {
    __shared__ float As[64][17];
    __shared__ float Bs[64][17];
    __shared__ int s_bt[64];
    __shared__ int s_eoff[64];

    int tid = threadIdx.x;
    int nrows = g_nrows;
    int r0 = blockIdx.x * 64;
    if (r0 >= nrows) return;
    int n0 = blockIdx.y * 64;

    if (tid < 64) {
        int r = r0 + tid;
        if (r < nrows) { s_bt[tid] = g_rows[r]; s_eoff[tid] = g_erow[r] * Ee; }
        else           { s_bt[tid] = -1;        s_eoff[tid] = 0; }
    }
    __syncthreads();

    const float* W1 = Wih + Gg * Ee;   // layer 1 slice of [L,G,E]
    int rl = tid >> 2, kq = (tid & 3) << 2;
    int ty = tid >> 4, tx = tid & 15;

    float acc[4][4];
#pragma unroll
    for (int i = 0; i < 4; i++)
#pragma unroll
        for (int j = 0; j < 4; j++) acc[i][j] = 0.0f;

    for (int kk = 0; kk < Ee; kk += 16) {
        float4 av = *(const float4*)(embt + s_eoff[rl] + kk + kq);
        float4 bv = *(const float4*)(W1 + (n0 + rl) * Ee + kk + kq);
        As[rl][kq + 0] = av.x; As[rl][kq + 1] = av.y; As[rl][kq + 2] = av.z; As[rl][kq + 3] = av.w;
        Bs[rl][kq + 0] = bv.x; Bs[rl][kq + 1] = bv.y; Bs[rl][kq + 2] = bv.z; Bs[rl][kq + 3] = bv.w;
        __syncthreads();
#pragma unroll
        for (int k = 0; k < 16; k++) {
            float a[4], b[4];
#pragma unroll
            for (int i = 0; i < 4; i++) a[i] = As[ty * 4 + i][k];
#pragma unroll
            for (int j = 0; j < 4; j++) b[j] = Bs[tx * 4 + j][k];
#pragma unroll
            for (int i = 0; i < 4; i++)
#pragma unroll
                for (int j = 0; j < 4; j++) acc[i][j] = fmaf(a[i], b[j], acc[i][j]);
        }
        __syncthreads();
    }

#pragma unroll
    for (int i = 0; i < 4; i++) {
        int meta = s_bt[ty * 4 + i];
        if (meta < 0) continue;
        int b = meta >> 6, t = meta & 63;
        float* dst = g_xproj + ((t * Bb) + b) * Gg + n0;
#pragma unroll
        for (int j = 0; j < 4; j++) {
            int n = tx * 4 + j;
            dst[n] = acc[i][j] + bih[Gg + n0 + n];
        }
    }
}

// ---------------- K2: recurrent gate GEMM for step t (active batches only) ----
// gates[b, n] = xproj[t,b,n] + dot(h_prev[b,:], W_hh[1][n][:]) + b_hh[1][n]
// Tile: 32(M) x 64(N), BK=32, 256 threads, 2x4 per thread.
__global__ void k2_gates(int t,
                         const float* __restrict__ Whh,
                         const float* __restrict__ bhh) {
    int cnt = g_actcnt[t];
    int m0 = blockIdx.x * 32;
    if (m0 >= cnt) return;
    int n0 = blockIdx.y * 64;

    __shared__ float As[32][33];
    __shared__ float Bs[64][33];
    __shared__ int s_b[32];

    int tid = threadIdx.x;
    if (tid < 32) {
        int mi = m0 + tid;
        s_b[tid] = (mi < cnt) ? g_act[t * Bb + mi] : -1;
    }
    __syncthreads();

    const float* W1 = Whh + Gg * Hh;   // layer 1 slice of [L,G,H]
    int rl = tid >> 3, kq = (tid & 7) << 2;
    int ty = tid >> 4, tx = tid & 15;
    int hoff = (s_b[rl] < 0 ? 0 : s_b[rl]) * Hh;

    float acc[2][4];
#pragma unroll
    for (int i = 0; i < 2; i++)
#pragma unroll
        for (int j = 0; j < 4; j++) acc[i][j] = 0.0f;

    for (int kk = 0; kk < Hh; kk += 32) {
        float4 av  = *(const float4*)(g_h + hoff + kk + kq);
        float4 bv0 = *(const float4*)(W1 + (n0 + rl) * Hh + kk + kq);
        float4 bv1 = *(const float4*)(W1 + (n0 + rl + 32) * Hh + kk + kq);
        As[rl][kq + 0] = av.x;  As[rl][kq + 1] = av.y;  As[rl][kq + 2] = av.z;  As[rl][kq + 3] = av.w;
        Bs[rl][kq + 0] = bv0.x; Bs[rl][kq + 1] = bv0.y; Bs[rl][kq + 2] = bv0.z; Bs[rl][kq + 3] = bv0.w;
        Bs[rl + 32][kq + 0] = bv1.x; Bs[rl + 32][kq + 1] = bv1.y; Bs[rl + 32][kq + 2] = bv1.z; Bs[rl + 32][kq + 3] = bv1.w;
        __syncthreads();
#pragma unroll
        for (int k = 0; k < 32; k++) {
            float a[2], b[4];
#pragma unroll
            for (int i = 0; i < 2; i++) a[i] = As[ty * 2 + i][k];
#pragma unroll
            for (int j = 0; j < 4; j++) b[j] = Bs[tx * 4 + j][k];
#pragma unroll
            for (int i = 0; i < 2; i++)
#pragma unroll
                for (int j = 0; j < 4; j++) acc[i][j] = fmaf(a[i], b[j], acc[i][j]);
        }
        __syncthreads();
    }

#pragma unroll
    for (int i = 0; i < 2; i++) {
        int b = s_b[ty * 2 + i];
        if (b < 0) continue;
        const float* xp = g_xproj + ((t * Bb) + b) * Gg + n0;
        float* gg = g_gates + b * Gg + n0;
#pragma unroll
        for (int j = 0; j < 4; j++) {
            int n = tx * 4 + j;
            gg[n] = acc[i][j] + xp[n] + bhh[Gg + n0 + n];
        }
    }
}

// ---------------- K3: LSTM cell + dual layernorm for step t -------------------
__global__ void k3_cell(int t,
                        const float* __restrict__ gamma_h, const float* __restrict__ beta_h,
                        const float* __restrict__ gamma_c, const float* __restrict__ beta_c,
                        float* __restrict__ out) {
    int m = blockIdx.x;
    int cnt = g_actcnt[t];
    if (m >= cnt) return;
    int b = g_act[t * Bb + m];
    int tid = threadIdx.x;

    __shared__ float sh[Hh];
    __shared__ float sc[Hh];
    __shared__ float4 red[256];

    float ph = 0.f, ph2 = 0.f, pc = 0.f, pc2 = 0.f;
    const float* gbase = g_gates + b * Gg;
    for (int j = tid; j < Hh; j += 256) {
        float ig = gbase[j];
        float fg = gbase[Hh + j];
        float gg = gbase[2 * Hh + j];
        float og = gbase[3 * Hh + j];
        float cprev = g_c[b * Hh + j];
        float cn = sigf(fg) * cprev + sigf(ig) * tanhf(gg);
        float hr = sigf(og) * tanhf(cn);
        sh[j] = hr; sc[j] = cn;
        ph += hr; ph2 += hr * hr; pc += cn; pc2 += cn * cn;
    }
    red[tid] = make_float4(ph, ph2, pc, pc2);
    __syncthreads();
    for (int s = 128; s > 0; s >>= 1) {
        if (tid < s) {
            float4 o = red[tid + s];
            float4 me = red[tid];
            me.x += o.x; me.y += o.y; me.z += o.z; me.w += o.w;
            red[tid] = me;
        }
        __syncthreads();
    }
    float4 tot = red[0];
    float inv_n = 1.0f / (float)Hh;
    float mu_h = tot.x * inv_n;
    float var_h = tot.y * inv_n - mu_h * mu_h;
    float mu_c = tot.z * inv_n;
    float var_c = tot.w * inv_n - mu_c * mu_c;
    float rs_h = rsqrtf(var_h + 1e-5f);
    float rs_c = rsqrtf(var_c + 1e-5f);

    bool is_last = (t == g_len[b] - 1);
    for (int j = tid; j < Hh; j += 256) {
        float hv = (sh[j] - mu_h) * rs_h * gamma_h[j] + beta_h[j];
        float cv = (sc[j] - mu_c) * rs_c * gamma_c[j] + beta_c[j];
        g_h[b * Hh + j] = hv;
        g_c[b * Hh + j] = cv;
        if (is_last) out[b * Hh + j] = hv;
    }
}

// ---------------- host launcher (graph-capturable) ----------------------------
extern "C" void kernel_launch(void* const* d_in, const int* in_sizes, int n_in,
                              void* d_out, int out_size) {
    const int*   msg  = (const int*)d_in[0];
    const int*   mlen = (const int*)d_in[1];
    const float* embt = (const float*)d_in[2];
    const float* Wih  = (const float*)d_in[3];
    const float* Whh  = (const float*)d_in[4];
    const float* bih  = (const float*)d_in[5];
    const float* bhh  = (const float*)d_in[6];
    const float* gmh  = (const float*)d_in[7];
    const float* bth  = (const float*)d_in[8];
    const float* gmc  = (const float*)d_in[9];
    const float* btc  = (const float*)d_in[10];
    float* out = (float*)d_out;

    void* hp; cudaGetSymbolAddress(&hp, g_h);
    void* cp; cudaGetSymbolAddress(&cp, g_c);
    cudaMemsetAsync(hp, 0, Bb * Hh * sizeof(float));
    cudaMemsetAsync(cp, 0, Bb * Hh * sizeof(float));

    k0_setup<<<1, 256>>>(msg, mlen);
    k1_xproj<<<dim3(Bb * Tt / 64, Gg / 64), 256>>>(embt, Wih, bih);
    for (int t = 0; t < Tt; t++) {
        k2_gates<<<dim3(Bb / 32, Gg / 64), 256>>>(t, Whh, bhh);
        k3_cell<<<Bb, 256>>>(t, gmh, bth, gmc, btc, out);
    }
}

// round 5
// speedup vs baseline: 3.0167x; 3.0167x over previous
#include <cuda_runtime.h>
#include <cuda_bf16.h>
#include <math.h>
#include <stdint.h>

// Problem constants
#define Bb 128
#define Tt 64
#define Ee 768
#define Hh 768
#define Gg 3072
#define NCTA 128      // persistent recurrence grid (1 CTA/SM, 128 co-resident)
#define WPAD 772      // padded k-stride for W shard (words)
#define HPAD 68       // padded k-stride for h staging (words)

// ---------------- device scratch (no allocations allowed) ----------------
__device__ int      g_len[Bb];
__device__ int      g_nrows;
__device__ int      g_rows[Bb * Tt];       // packed (b<<6)|t for active (b,t)
__device__ int      g_erow[Bb * Tt];       // token id per active row
__device__ float    g_xproj[Tt * Bb * Gg]; // [t][b][g] layer-1 input projection
__device__ uint32_t g_hpk[Bb * Hh];        // h packed as (lo_bf16<<16)|hi_bf16
__device__ float    g_c[Bb * Hh];
__device__ float    g_gates[Bb * Gg];
__device__ unsigned g_bar;

__device__ __forceinline__ float sigf(float x) { return 1.0f / (1.0f + expf(-x)); }

// split fp32 into bf16 hi/lo, pack into one word: bits[15:0]=hi, [31:16]=lo
__device__ __forceinline__ uint32_t pksplit(float v) {
    __nv_bfloat16 h = __float2bfloat16(v);
    float r = v - __bfloat162float(h);
    __nv_bfloat16 l = __float2bfloat16(r);
    return ((uint32_t)__bfloat16_as_ushort(l) << 16) | (uint32_t)__bfloat16_as_ushort(h);
}

// from packed words of elements k,k+1 build half2-style regs {hi(k),hi(k+1)} / {lo(k),lo(k+1)}
#define HIPAIR(u0, u1) __byte_perm((u0), (u1), 0x5410)
#define LOPAIR(u0, u1) __byte_perm((u0), (u1), 0x7632)

// m16n8k16 bf16 mma, row.col, f32 accumulate
__device__ __forceinline__ void mma16(float* c, const uint32_t* a, const uint32_t* b) {
    asm volatile("mma.sync.aligned.m16n8k16.row.col.f32.bf16.bf16.f32 "
        "{%0,%1,%2,%3}, {%4,%5,%6,%7}, {%8,%9}, {%0,%1,%2,%3};"
        : "+f"(c[0]), "+f"(c[1]), "+f"(c[2]), "+f"(c[3])
        : "r"(a[0]), "r"(a[1]), "r"(a[2]), "r"(a[3]), "r"(b[0]), "r"(b[1]));
}

__device__ __forceinline__ void cpa16(void* sdst, const void* g) {
    uint32_t sa = (uint32_t)__cvta_generic_to_shared(sdst);
    asm volatile("cp.async.cg.shared.global [%0], [%1], 16;" :: "r"(sa), "l"(g));
}

// ---------------- K0: dtype detect + length/active-row setup ----------------
__global__ void k0_setup(const int* __restrict__ msg, const int* __restrict__ mlen) {
    __shared__ int s_flag;
    __shared__ int s_nr;
    int tid = threadIdx.x;
    if (tid == 0) { s_flag = 0; s_nr = 0; g_bar = 0; }
    __syncthreads();

    int local = 0;
    for (int i = tid; i < (Bb * Tt) / 2; i += 256)
        if (msg[2 * i + 1] != 0) local = 1;
    if (local) atomicOr(&s_flag, 1);
    __syncthreads();
    int is64 = (s_flag == 0);

    if (tid < Bb) {
        int lb = is64 ? mlen[2 * tid] : mlen[tid];
        g_len[tid] = lb;
        for (int t = 0; t < lb; t++) {
            int r = atomicAdd(&s_nr, 1);
            g_rows[r] = (tid << 6) | t;
            int mi = tid * Tt + t;
            g_erow[r] = is64 ? msg[2 * mi] : msg[mi];
        }
    }
    __syncthreads();
    if (tid == 0) g_nrows = s_nr;
}

// ---------------- K1: input projection GEMM, bf16x3 split ----------------
// C[row=(b,t), n] = emb[token] . W_ih[1][n][:] + b_ih[1][n]
// Tile: 128m x 64n, K-chunk 32, 8 warps as 4m x 2n (warp tile 32m x 32n).
__global__ __launch_bounds__(256) void k1_xproj(const float* __restrict__ embt,
                                                const float* __restrict__ Wih,
                                                const float* __restrict__ bih) {
    __shared__ uint32_t As[128][36];
    __shared__ uint32_t Bs[64][36];
    __shared__ int s_bt[128];
    __shared__ int s_eoff[128];

    int tid = threadIdx.x;
    int nrows = g_nrows;
    int r0 = blockIdx.x * 128;
    if (r0 >= nrows) return;
    int n0 = blockIdx.y * 64;

    if (tid < 128) {
        int r = r0 + tid;
        if (r < nrows) { s_bt[tid] = g_rows[r]; s_eoff[tid] = g_erow[r] * Ee; }
        else           { s_bt[tid] = -1;        s_eoff[tid] = 0; }
    }

    const float* W1 = Wih + (size_t)Gg * Ee;   // layer 1
    int l = tid & 31, w = tid >> 5;
    int wm = w >> 1, wn = w & 1;

    float acc[2][4][4];
#pragma unroll
    for (int i = 0; i < 2; i++)
#pragma unroll
        for (int jn = 0; jn < 4; jn++)
#pragma unroll
            for (int q = 0; q < 4; q++) acc[i][jn][q] = 0.0f;

    int arow = tid >> 1, ak = (tid & 1) * 16;
    int brow = tid >> 2, bk = (tid & 3) * 8;

    for (int kk = 0; kk < Ee; kk += 32) {
        __syncthreads();
        const float* ap = embt + s_eoff[arow] + kk + ak;
#pragma unroll
        for (int i = 0; i < 4; i++) {
            float4 v = *(const float4*)(ap + 4 * i);
            As[arow][ak + 4 * i + 0] = pksplit(v.x);
            As[arow][ak + 4 * i + 1] = pksplit(v.y);
            As[arow][ak + 4 * i + 2] = pksplit(v.z);
            As[arow][ak + 4 * i + 3] = pksplit(v.w);
        }
        const float* bp = W1 + (size_t)(n0 + brow) * Ee + kk + bk;
#pragma unroll
        for (int i = 0; i < 2; i++) {
            float4 v = *(const float4*)(bp + 4 * i);
            Bs[brow][bk + 4 * i + 0] = pksplit(v.x);
            Bs[brow][bk + 4 * i + 1] = pksplit(v.y);
            Bs[brow][bk + 4 * i + 2] = pksplit(v.z);
            Bs[brow][bk + 4 * i + 3] = pksplit(v.w);
        }
        __syncthreads();
#pragma unroll
        for (int k16 = 0; k16 < 2; k16++) {
            int kp = k16 * 16 + (l & 3) * 2;
            uint32_t ahi[2][4], alo[2][4];
#pragma unroll
            for (int mt = 0; mt < 2; mt++) {
                int mb = wm * 32 + mt * 16 + (l >> 2);
                uint2 p0 = *(const uint2*)&As[mb][kp];
                uint2 p1 = *(const uint2*)&As[mb + 8][kp];
                uint2 p2 = *(const uint2*)&As[mb][kp + 8];
                uint2 p3 = *(const uint2*)&As[mb + 8][kp + 8];
                ahi[mt][0] = HIPAIR(p0.x, p0.y); alo[mt][0] = LOPAIR(p0.x, p0.y);
                ahi[mt][1] = HIPAIR(p1.x, p1.y); alo[mt][1] = LOPAIR(p1.x, p1.y);
                ahi[mt][2] = HIPAIR(p2.x, p2.y); alo[mt][2] = LOPAIR(p2.x, p2.y);
                ahi[mt][3] = HIPAIR(p3.x, p3.y); alo[mt][3] = LOPAIR(p3.x, p3.y);
            }
            uint32_t bhi[4][2], blo[4][2];
#pragma unroll
            for (int nt = 0; nt < 4; nt++) {
                int nb = wn * 32 + nt * 8 + (l >> 2);
                uint2 q0 = *(const uint2*)&Bs[nb][kp];
                uint2 q1 = *(const uint2*)&Bs[nb][kp + 8];
                bhi[nt][0] = HIPAIR(q0.x, q0.y); blo[nt][0] = LOPAIR(q0.x, q0.y);
                bhi[nt][1] = HIPAIR(q1.x, q1.y); blo[nt][1] = LOPAIR(q1.x, q1.y);
            }
#pragma unroll
            for (int mt = 0; mt < 2; mt++)
#pragma unroll
                for (int nt = 0; nt < 4; nt++) {
                    mma16(acc[mt][nt], ahi[mt], bhi[nt]);
                    mma16(acc[mt][nt], ahi[mt], blo[nt]);
                    mma16(acc[mt][nt], alo[mt], bhi[nt]);
                }
        }
    }

#pragma unroll
    for (int mt = 0; mt < 2; mt++) {
        int rbase = wm * 32 + mt * 16 + (l >> 2);
#pragma unroll
        for (int nt = 0; nt < 4; nt++) {
            int nc = n0 + wn * 32 + nt * 8 + 2 * (l & 3);
            float2 bias = *(const float2*)(bih + Gg + nc);
            int meta = s_bt[rbase];
            if (meta >= 0) {
                int b_ = meta >> 6, t_ = meta & 63;
                float2 o; o.x = acc[mt][nt][0] + bias.x; o.y = acc[mt][nt][1] + bias.y;
                *(float2*)(g_xproj + ((size_t)(t_ * Bb) + b_) * Gg + nc) = o;
            }
            meta = s_bt[rbase + 8];
            if (meta >= 0) {
                int b_ = meta >> 6, t_ = meta & 63;
                float2 o; o.x = acc[mt][nt][2] + bias.x; o.y = acc[mt][nt][3] + bias.y;
                *(float2*)(g_xproj + ((size_t)(t_ * Bb) + b_) * Gg + nc) = o;
            }
        }
    }
}

// ---------------- persistent recurrence kernel ----------------
__device__ __forceinline__ void grid_sync(unsigned target) {
    __syncthreads();
    if (threadIdx.x == 0) {
        __threadfence();
        atomicAdd(&g_bar, 1u);
        while (*(volatile unsigned*)&g_bar < target) { }
        __threadfence();
    }
    __syncthreads();
}

extern __shared__ uint32_t dsm[];   // [w_sh 48*772][hs 2*64*68] (cell scratch overlays hs)

__global__ __launch_bounds__(256, 1) void krec(
        const float* __restrict__ Whh, const float* __restrict__ bhh,
        const float* __restrict__ gmh, const float* __restrict__ bth,
        const float* __restrict__ gmc, const float* __restrict__ btc,
        float* __restrict__ out) {
    uint32_t* w_sh = dsm;                           // 48 x WPAD packed bf16x2
    uint32_t* hs   = dsm + 48 * WPAD;               // 2 x (64 x HPAD) packed bf16x2
    float* cellf   = (float*)(dsm + 48 * WPAD);     // phase-B overlay

    int tid = threadIdx.x;
    int bg = blockIdx.x >> 6;        // batch group (0/1): batches bg*64..+63
    int shard = blockIdx.x & 63;     // N-shard: cols shard*48..+47
    int j = blockIdx.x;              // phase-B batch

    // Load W_hh[1] shard into SMEM (packed bf16 hi/lo), once for all 64 steps.
    const float* W1 = Whh + (size_t)Gg * Hh + (size_t)shard * 48 * Hh;
    for (int i = tid; i < 48 * (Hh / 4); i += 256) {
        int n = i / (Hh / 4), kq = (i % (Hh / 4)) * 4;
        float4 v = *(const float4*)(W1 + (size_t)n * Hh + kq);
        uint32_t* d = &w_sh[n * WPAD + kq];
        d[0] = pksplit(v.x); d[1] = pksplit(v.y); d[2] = pksplit(v.z); d[3] = pksplit(v.w);
    }

    int l = tid & 31, w = tid >> 5;
    int wm = w >> 1, wn = w & 1;             // 4 m-warps x 2 n-warps; warp tile 16m x 24n
    int srow = tid & 63, skq = (tid >> 6) * 16;
    const uint32_t* hsrc_base = g_hpk + (size_t)(bg * 64 + srow) * Hh + skq;
    uint32_t* sdst = hs + srow * HPAD + skq;

    unsigned sync_no = 0;

    for (int t = 0; t < Tt; t++) {
        // ---- phase A: gates[bg*64..+63][shard*48..+47] = h . Whh_shard^T (bf16x3) ----
        float acc[3][4];
#pragma unroll
        for (int i = 0; i < 3; i++)
#pragma unroll
            for (int q = 0; q < 4; q++) acc[i][q] = 0.0f;

        { // prefetch k-chunk 0 of packed h
#pragma unroll
            for (int i = 0; i < 4; i++) cpa16(sdst + 4 * i, hsrc_base + 4 * i);
            asm volatile("cp.async.commit_group;");
        }
#pragma unroll 1
        for (int c = 0; c < 12; c++) {
            if (c < 11) {
                const uint32_t* src = hsrc_base + (c + 1) * 64;
                uint32_t* dst = sdst + ((c + 1) & 1) * (64 * HPAD);
#pragma unroll
                for (int i = 0; i < 4; i++) cpa16(dst + 4 * i, src + 4 * i);
                asm volatile("cp.async.commit_group;");
                asm volatile("cp.async.wait_group 1;");
            } else {
                asm volatile("cp.async.wait_group 0;");
            }
            __syncthreads();
            const uint32_t* hb = hs + (c & 1) * (64 * HPAD);
#pragma unroll
            for (int k16 = 0; k16 < 4; k16++) {
                int kp = k16 * 16 + (l & 3) * 2;
                uint32_t ahi[4], alo[4];
                {
                    int ar = wm * 16 + (l >> 2);
                    uint2 p0 = *(const uint2*)&hb[ar * HPAD + kp];
                    uint2 p1 = *(const uint2*)&hb[(ar + 8) * HPAD + kp];
                    uint2 p2 = *(const uint2*)&hb[ar * HPAD + kp + 8];
                    uint2 p3 = *(const uint2*)&hb[(ar + 8) * HPAD + kp + 8];
                    ahi[0] = HIPAIR(p0.x, p0.y); alo[0] = LOPAIR(p0.x, p0.y);
                    ahi[1] = HIPAIR(p1.x, p1.y); alo[1] = LOPAIR(p1.x, p1.y);
                    ahi[2] = HIPAIR(p2.x, p2.y); alo[2] = LOPAIR(p2.x, p2.y);
                    ahi[3] = HIPAIR(p3.x, p3.y); alo[3] = LOPAIR(p3.x, p3.y);
                }
                int kg = c * 64 + kp;
#pragma unroll
                for (int nt = 0; nt < 3; nt++) {
                    int nr = wn * 24 + nt * 8 + (l >> 2);
                    uint2 q0 = *(const uint2*)&w_sh[nr * WPAD + kg];
                    uint2 q1 = *(const uint2*)&w_sh[nr * WPAD + kg + 8];
                    uint32_t bhi[2], blo[2];
                    bhi[0] = HIPAIR(q0.x, q0.y); blo[0] = LOPAIR(q0.x, q0.y);
                    bhi[1] = HIPAIR(q1.x, q1.y); blo[1] = LOPAIR(q1.x, q1.y);
                    mma16(acc[nt], ahi, bhi);
                    mma16(acc[nt], ahi, blo);
                    mma16(acc[nt], alo, bhi);
                }
            }
            __syncthreads();
        }
        { // epilogue: gates = acc + xproj[t] + b_hh[1]
            int r_ = wm * 16 + (l >> 2);
            int b0_ = bg * 64 + r_;
            int b1_ = b0_ + 8;
#pragma unroll
            for (int nt = 0; nt < 3; nt++) {
                int nc = shard * 48 + wn * 24 + nt * 8 + 2 * (l & 3);
                float2 bias = *(const float2*)(bhh + Gg + nc);
                float2 xp = *(const float2*)(g_xproj + ((size_t)(t * Bb) + b0_) * Gg + nc);
                float2 o;
                o.x = acc[nt][0] + xp.x + bias.x;
                o.y = acc[nt][1] + xp.y + bias.y;
                *(float2*)(g_gates + (size_t)b0_ * Gg + nc) = o;
                xp = *(const float2*)(g_xproj + ((size_t)(t * Bb) + b1_) * Gg + nc);
                o.x = acc[nt][2] + xp.x + bias.x;
                o.y = acc[nt][3] + xp.y + bias.y;
                *(float2*)(g_gates + (size_t)b1_ * Gg + nc) = o;
            }
        }
        grid_sync(++sync_no * NCTA);

        // ---- phase B: LSTM cell + dual LN for batch j (skip once past length) ----
        if (t < g_len[j]) {
            float* shh = cellf;
            float* scc = cellf + Hh;
            float* red = cellf + 2 * Hh;   // 36 floats
            float ph = 0.f, ph2 = 0.f, pc = 0.f, pc2 = 0.f;
            const float* gb = g_gates + (size_t)j * Gg;
            float* cj = g_c + (size_t)j * Hh;
            for (int jj = tid; jj < Hh; jj += 256) {
                float ig = gb[jj], fg = gb[Hh + jj], gg = gb[2 * Hh + jj], og = gb[3 * Hh + jj];
                float cn = sigf(fg) * cj[jj] + sigf(ig) * tanhf(gg);
                float hr = sigf(og) * tanhf(cn);
                shh[jj] = hr; scc[jj] = cn;
                ph += hr; ph2 += hr * hr; pc += cn; pc2 += cn * cn;
            }
#pragma unroll
            for (int o = 16; o; o >>= 1) {
                ph  += __shfl_down_sync(0xffffffffu, ph, o);
                ph2 += __shfl_down_sync(0xffffffffu, ph2, o);
                pc  += __shfl_down_sync(0xffffffffu, pc, o);
                pc2 += __shfl_down_sync(0xffffffffu, pc2, o);
            }
            if (l == 0) { red[w * 4 + 0] = ph; red[w * 4 + 1] = ph2; red[w * 4 + 2] = pc; red[w * 4 + 3] = pc2; }
            __syncthreads();
            if (tid == 0) {
                float a0 = 0, a1 = 0, a2 = 0, a3 = 0;
                for (int i = 0; i < 8; i++) { a0 += red[4 * i]; a1 += red[4 * i + 1]; a2 += red[4 * i + 2]; a3 += red[4 * i + 3]; }
                red[32] = a0; red[33] = a1; red[34] = a2; red[35] = a3;
            }
            __syncthreads();
            const float inv = 1.0f / 768.0f;
            float muh = red[32] * inv, varh = red[33] * inv - muh * muh;
            float muc = red[34] * inv, varc = red[35] * inv - muc * muc;
            float rsh = rsqrtf(varh + 1e-5f), rsc = rsqrtf(varc + 1e-5f);
            bool last = (t == g_len[j] - 1);
            for (int jj = tid; jj < Hh; jj += 256) {
                float hv = (shh[jj] - muh) * rsh * gmh[jj] + bth[jj];
                float cv = (scc[jj] - muc) * rsc * gmc[jj] + btc[jj];
                g_hpk[(size_t)j * Hh + jj] = pksplit(hv);
                cj[jj] = cv;
                if (last) out[(size_t)j * Hh + jj] = hv;
            }
        }
        grid_sync(++sync_no * NCTA);
    }
}

// ---------------- host launcher (graph-capturable) ----------------
extern "C" void kernel_launch(void* const* d_in, const int* in_sizes, int n_in,
                              void* d_out, int out_size) {
    const int*   msg  = (const int*)d_in[0];
    const int*   mlen = (const int*)d_in[1];
    const float* embt = (const float*)d_in[2];
    const float* Wih  = (const float*)d_in[3];
    const float* Whh  = (const float*)d_in[4];
    const float* bih  = (const float*)d_in[5];
    const float* bhh  = (const float*)d_in[6];
    const float* gmh  = (const float*)d_in[7];
    const float* bth  = (const float*)d_in[8];
    const float* gmc  = (const float*)d_in[9];
    const float* btc  = (const float*)d_in[10];
    float* out = (float*)d_out;

    void* hp; cudaGetSymbolAddress(&hp, g_hpk);
    void* cp; cudaGetSymbolAddress(&cp, g_c);
    cudaMemsetAsync(hp, 0, Bb * Hh * sizeof(uint32_t));
    cudaMemsetAsync(cp, 0, Bb * Hh * sizeof(float));

    k0_setup<<<1, 256>>>(msg, mlen);
    k1_xproj<<<dim3(64, 48), 256>>>(embt, Wih, bih);

    size_t smem = (size_t)(48 * WPAD + 2 * 64 * HPAD) * sizeof(uint32_t);  // 183,040 B
    cudaFuncSetAttribute(krec, cudaFuncAttributeMaxDynamicSharedMemorySize, (int)smem);
    krec<<<NCTA, 256, smem>>>(Whh, bhh, gmh, bth, gmc, btc, out);
}

// round 6
// speedup vs baseline: 3.0597x; 1.0143x over previous
#include <cuda_runtime.h>
#include <cuda_bf16.h>
#include <math.h>
#include <stdint.h>

// Problem constants
#define Bb 128
#define Tt 64
#define Ee 768
#define Hh 768
#define Gg 3072
#define NCTA 128      // persistent recurrence grid (1 CTA/SM, 128 co-resident)
#define WPAD 772      // padded k-stride for W shard (words)
#define HPAD 68       // padded k-stride for h staging (words)

// ---------------- device scratch (no allocations allowed) ----------------
__device__ int      g_len[Bb];
__device__ int      g_nrows;
__device__ int      g_rows[Bb * Tt];       // packed (b<<6)|t for active (b,t)
__device__ int      g_erow[Bb * Tt];       // token id per active row
__device__ float    g_xproj[Tt * Bb * Gg]; // [t][b][g] layer-1 input projection
__device__ uint32_t g_hpk[Bb * Hh];        // h packed as (lo_bf16<<16)|hi_bf16
__device__ float    g_c[Bb * Hh];
__device__ float    g_gates[Bb * Gg];
__device__ unsigned g_bar;

__device__ __forceinline__ float sigf(float x) { return 1.0f / (1.0f + expf(-x)); }

// split fp32 into bf16 hi/lo, pack into one word: bits[15:0]=hi, [31:16]=lo
__device__ __forceinline__ uint32_t pksplit(float v) {
    __nv_bfloat16 h = __float2bfloat16(v);
    float r = v - __bfloat162float(h);
    __nv_bfloat16 l = __float2bfloat16(r);
    return ((uint32_t)__bfloat16_as_ushort(l) << 16) | (uint32_t)__bfloat16_as_ushort(h);
}

// from packed words of elements k,k+1 build half2-style regs {hi(k),hi(k+1)} / {lo(k),lo(k+1)}
#define HIPAIR(u0, u1) __byte_perm((u0), (u1), 0x5410)
#define LOPAIR(u0, u1) __byte_perm((u0), (u1), 0x7632)

// m16n8k16 bf16 mma, row.col, f32 accumulate
__device__ __forceinline__ void mma16(float* c, const uint32_t* a, const uint32_t* b) {
    asm volatile("mma.sync.aligned.m16n8k16.row.col.f32.bf16.bf16.f32 "
        "{%0,%1,%2,%3}, {%4,%5,%6,%7}, {%8,%9}, {%0,%1,%2,%3};"
        : "+f"(c[0]), "+f"(c[1]), "+f"(c[2]), "+f"(c[3])
        : "r"(a[0]), "r"(a[1]), "r"(a[2]), "r"(a[3]), "r"(b[0]), "r"(b[1]));
}

__device__ __forceinline__ void cpa16(void* sdst, const void* g) {
    uint32_t sa = (uint32_t)__cvta_generic_to_shared(sdst);
    asm volatile("cp.async.cg.shared.global [%0], [%1], 16;" :: "r"(sa), "l"(g));
}

// ---------------- K0: dtype detect + length/active-row setup ----------------
__global__ void k0_setup(const int* __restrict__ msg, const int* __restrict__ mlen) {
    __shared__ int s_flag;
    __shared__ int s_nr;
    int tid = threadIdx.x;
    if (tid == 0) { s_flag = 0; s_nr = 0; g_bar = 0; }
    __syncthreads();

    int local = 0;
    for (int i = tid; i < (Bb * Tt) / 2; i += 256)
        if (msg[2 * i + 1] != 0) local = 1;
    if (local) atomicOr(&s_flag, 1);
    __syncthreads();
    int is64 = (s_flag == 0);

    if (tid < Bb) {
        int lb = is64 ? mlen[2 * tid] : mlen[tid];
        g_len[tid] = lb;
        for (int t = 0; t < lb; t++) {
            int r = atomicAdd(&s_nr, 1);
            g_rows[r] = (tid << 6) | t;
            int mi = tid * Tt + t;
            g_erow[r] = is64 ? msg[2 * mi] : msg[mi];
        }
    }
    __syncthreads();
    if (tid == 0) g_nrows = s_nr;
}

// ---------------- K1: input projection GEMM, bf16x3 split ----------------
// C[row=(b,t), n] = emb[token] . W_ih[1][n][:] + b_ih[1][n]
// Tile: 128m x 64n, K-chunk 32, 8 warps as 4m x 2n (warp tile 32m x 32n).
__global__ __launch_bounds__(256) void k1_xproj(const float* __restrict__ embt,
                                                const float* __restrict__ Wih,
                                                const float* __restrict__ bih) {
    __shared__ uint32_t As[128][36];
    __shared__ uint32_t Bs[64][36];
    __shared__ int s_bt[128];
    __shared__ int s_eoff[128];

    int tid = threadIdx.x;
    int nrows = g_nrows;
    int r0 = blockIdx.x * 128;
    if (r0 >= nrows) return;
    int n0 = blockIdx.y * 64;

    if (tid < 128) {
        int r = r0 + tid;
        if (r < nrows) { s_bt[tid] = g_rows[r]; s_eoff[tid] = g_erow[r] * Ee; }
        else           { s_bt[tid] = -1;        s_eoff[tid] = 0; }
    }

    const float* W1 = Wih + (size_t)Gg * Ee;   // layer 1
    int l = tid & 31, w = tid >> 5;
    int wm = w >> 1, wn = w & 1;

    float acc[2][4][4];
#pragma unroll
    for (int i = 0; i < 2; i++)
#pragma unroll
        for (int jn = 0; jn < 4; jn++)
#pragma unroll
            for (int q = 0; q < 4; q++) acc[i][jn][q] = 0.0f;

    int arow = tid >> 1, ak = (tid & 1) * 16;
    int brow = tid >> 2, bk = (tid & 3) * 8;

    for (int kk = 0; kk < Ee; kk += 32) {
        __syncthreads();
        const float* ap = embt + s_eoff[arow] + kk + ak;
#pragma unroll
        for (int i = 0; i < 4; i++) {
            float4 v = *(const float4*)(ap + 4 * i);
            As[arow][ak + 4 * i + 0] = pksplit(v.x);
            As[arow][ak + 4 * i + 1] = pksplit(v.y);
            As[arow][ak + 4 * i + 2] = pksplit(v.z);
            As[arow][ak + 4 * i + 3] = pksplit(v.w);
        }
        const float* bp = W1 + (size_t)(n0 + brow) * Ee + kk + bk;
#pragma unroll
        for (int i = 0; i < 2; i++) {
            float4 v = *(const float4*)(bp + 4 * i);
            Bs[brow][bk + 4 * i + 0] = pksplit(v.x);
            Bs[brow][bk + 4 * i + 1] = pksplit(v.y);
            Bs[brow][bk + 4 * i + 2] = pksplit(v.z);
            Bs[brow][bk + 4 * i + 3] = pksplit(v.w);
        }
        __syncthreads();
#pragma unroll
        for (int k16 = 0; k16 < 2; k16++) {
            int kp = k16 * 16 + (l & 3) * 2;
            uint32_t ahi[2][4], alo[2][4];
#pragma unroll
            for (int mt = 0; mt < 2; mt++) {
                int mb = wm * 32 + mt * 16 + (l >> 2);
                uint2 p0 = *(const uint2*)&As[mb][kp];
                uint2 p1 = *(const uint2*)&As[mb + 8][kp];
                uint2 p2 = *(const uint2*)&As[mb][kp + 8];
                uint2 p3 = *(const uint2*)&As[mb + 8][kp + 8];
                ahi[mt][0] = HIPAIR(p0.x, p0.y); alo[mt][0] = LOPAIR(p0.x, p0.y);
                ahi[mt][1] = HIPAIR(p1.x, p1.y); alo[mt][1] = LOPAIR(p1.x, p1.y);
                ahi[mt][2] = HIPAIR(p2.x, p2.y); alo[mt][2] = LOPAIR(p2.x, p2.y);
                ahi[mt][3] = HIPAIR(p3.x, p3.y); alo[mt][3] = LOPAIR(p3.x, p3.y);
            }
            uint32_t bhi[4][2], blo[4][2];
#pragma unroll
            for (int nt = 0; nt < 4; nt++) {
                int nb = wn * 32 + nt * 8 + (l >> 2);
                uint2 q0 = *(const uint2*)&Bs[nb][kp];
                uint2 q1 = *(const uint2*)&Bs[nb][kp + 8];
                bhi[nt][0] = HIPAIR(q0.x, q0.y); blo[nt][0] = LOPAIR(q0.x, q0.y);
                bhi[nt][1] = HIPAIR(q1.x, q1.y); blo[nt][1] = LOPAIR(q1.x, q1.y);
            }
#pragma unroll
            for (int mt = 0; mt < 2; mt++)
#pragma unroll
                for (int nt = 0; nt < 4; nt++) {
                    mma16(acc[mt][nt], ahi[mt], bhi[nt]);
                    mma16(acc[mt][nt], ahi[mt], blo[nt]);
                    mma16(acc[mt][nt], alo[mt], bhi[nt]);
                }
        }
    }

#pragma unroll
    for (int mt = 0; mt < 2; mt++) {
        int rbase = wm * 32 + mt * 16 + (l >> 2);
#pragma unroll
        for (int nt = 0; nt < 4; nt++) {
            int nc = n0 + wn * 32 + nt * 8 + 2 * (l & 3);
            float2 bias = *(const float2*)(bih + Gg + nc);
            int meta = s_bt[rbase];
            if (meta >= 0) {
                int b_ = meta >> 6, t_ = meta & 63;
                float2 o; o.x = acc[mt][nt][0] + bias.x; o.y = acc[mt][nt][1] + bias.y;
                *(float2*)(g_xproj + ((size_t)(t_ * Bb) + b_) * Gg + nc) = o;
            }
            meta = s_bt[rbase + 8];
            if (meta >= 0) {
                int b_ = meta >> 6, t_ = meta & 63;
                float2 o; o.x = acc[mt][nt][2] + bias.x; o.y = acc[mt][nt][3] + bias.y;
                *(float2*)(g_xproj + ((size_t)(t_ * Bb) + b_) * Gg + nc) = o;
            }
        }
    }
}

// ---------------- persistent recurrence kernel ----------------
__device__ __forceinline__ void grid_sync(unsigned target) {
    __syncthreads();
    if (threadIdx.x == 0) {
        __threadfence();
        atomicAdd(&g_bar, 1u);
        while (*(volatile unsigned*)&g_bar < target) { }
        __threadfence();
    }
    __syncthreads();
}

extern __shared__ uint32_t dsm[];   // [w_sh 48*772][hs 2*64*68] (cell scratch overlays hs)

__global__ __launch_bounds__(256, 1) void krec(
        const float* __restrict__ Whh, const float* __restrict__ bhh,
        const float* __restrict__ gmh, const float* __restrict__ bth,
        const float* __restrict__ gmc, const float* __restrict__ btc,
        float* __restrict__ out) {
    uint32_t* w_sh = dsm;                           // 48 x WPAD packed bf16x2
    uint32_t* hs   = dsm + 48 * WPAD;               // 2 x (64 x HPAD) packed bf16x2
    float* cellf   = (float*)(dsm + 48 * WPAD);     // phase-B overlay

    int tid = threadIdx.x;
    int bg = blockIdx.x >> 6;        // batch group (0/1): batches bg*64..+63
    int shard = blockIdx.x & 63;     // N-shard: cols shard*48..+47
    int j = blockIdx.x;              // phase-B batch

    // Load W_hh[1] shard into SMEM (packed bf16 hi/lo), once for all 64 steps.
    const float* W1 = Whh + (size_t)Gg * Hh + (size_t)shard * 48 * Hh;
    for (int i = tid; i < 48 * (Hh / 4); i += 256) {
        int n = i / (Hh / 4), kq = (i % (Hh / 4)) * 4;
        float4 v = *(const float4*)(W1 + (size_t)n * Hh + kq);
        uint32_t* d = &w_sh[n * WPAD + kq];
        d[0] = pksplit(v.x); d[1] = pksplit(v.y); d[2] = pksplit(v.z); d[3] = pksplit(v.w);
    }

    int l = tid & 31, w = tid >> 5;
    int wm = w >> 1, wn = w & 1;             // 4 m-warps x 2 n-warps; warp tile 16m x 24n
    int srow = tid & 63, skq = (tid >> 6) * 16;
    const uint32_t* hsrc_base = g_hpk + (size_t)(bg * 64 + srow) * Hh + skq;
    uint32_t* sdst = hs + srow * HPAD + skq;

    unsigned sync_no = 0;

    for (int t = 0; t < Tt; t++) {
        // ---- phase A: gates[bg*64..+63][shard*48..+47] = h . Whh_shard^T (bf16x3) ----
        float acc[3][4];
#pragma unroll
        for (int i = 0; i < 3; i++)
#pragma unroll
            for (int q = 0; q < 4; q++) acc[i][q] = 0.0f;

        { // prefetch k-chunk 0 of packed h
#pragma unroll
            for (int i = 0; i < 4; i++) cpa16(sdst + 4 * i, hsrc_base + 4 * i);
            asm volatile("cp.async.commit_group;");
        }
#pragma unroll 1
        for (int c = 0; c < 12; c++) {
            if (c < 11) {
                const uint32_t* src = hsrc_base + (c + 1) * 64;
                uint32_t* dst = sdst + ((c + 1) & 1) * (64 * HPAD);
#pragma unroll
                for (int i = 0; i < 4; i++) cpa16(dst + 4 * i, src + 4 * i);
                asm volatile("cp.async.commit_group;");
                asm volatile("cp.async.wait_group 1;");
            } else {
                asm volatile("cp.async.wait_group 0;");
            }
            __syncthreads();
            const uint32_t* hb = hs + (c & 1) * (64 * HPAD);
#pragma unroll
            for (int k16 = 0; k16 < 4; k16++) {
                int kp = k16 * 16 + (l & 3) * 2;
                uint32_t ahi[4], alo[4];
                {
                    int ar = wm * 16 + (l >> 2);
                    uint2 p0 = *(const uint2*)&hb[ar * HPAD + kp];
                    uint2 p1 = *(const uint2*)&hb[(ar + 8) * HPAD + kp];
                    uint2 p2 = *(const uint2*)&hb[ar * HPAD + kp + 8];
                    uint2 p3 = *(const uint2*)&hb[(ar + 8) * HPAD + kp + 8];
                    ahi[0] = HIPAIR(p0.x, p0.y); alo[0] = LOPAIR(p0.x, p0.y);
                    ahi[1] = HIPAIR(p1.x, p1.y); alo[1] = LOPAIR(p1.x, p1.y);
                    ahi[2] = HIPAIR(p2.x, p2.y); alo[2] = LOPAIR(p2.x, p2.y);
                    ahi[3] = HIPAIR(p3.x, p3.y); alo[3] = LOPAIR(p3.x, p3.y);
                }
                int kg = c * 64 + kp;
#pragma unroll
                for (int nt = 0; nt < 3; nt++) {
                    int nr = wn * 24 + nt * 8 + (l >> 2);
                    uint2 q0 = *(const uint2*)&w_sh[nr * WPAD + kg];
                    uint2 q1 = *(const uint2*)&w_sh[nr * WPAD + kg + 8];
                    uint32_t bhi[2], blo[2];
                    bhi[0] = HIPAIR(q0.x, q0.y); blo[0] = LOPAIR(q0.x, q0.y);
                    bhi[1] = HIPAIR(q1.x, q1.y); blo[1] = LOPAIR(q1.x, q1.y);
                    mma16(acc[nt], ahi, bhi);
                    mma16(acc[nt], ahi, blo);
                    mma16(acc[nt], alo, bhi);
                }
            }
            __syncthreads();
        }
        { // epilogue: gates = acc + xproj[t] + b_hh[1]
            int r_ = wm * 16 + (l >> 2);
            int b0_ = bg * 64 + r_;
            int b1_ = b0_ + 8;
#pragma unroll
            for (int nt = 0; nt < 3; nt++) {
                int nc = shard * 48 + wn * 24 + nt * 8 + 2 * (l & 3);
                float2 bias = *(const float2*)(bhh + Gg + nc);
                float2 xp = *(const float2*)(g_xproj + ((size_t)(t * Bb) + b0_) * Gg + nc);
                float2 o;
                o.x = acc[nt][0] + xp.x + bias.x;
                o.y = acc[nt][1] + xp.y + bias.y;
                *(float2*)(g_gates + (size_t)b0_ * Gg + nc) = o;
                xp = *(const float2*)(g_xproj + ((size_t)(t * Bb) + b1_) * Gg + nc);
                o.x = acc[nt][2] + xp.x + bias.x;
                o.y = acc[nt][3] + xp.y + bias.y;
                *(float2*)(g_gates + (size_t)b1_ * Gg + nc) = o;
            }
        }
        grid_sync(++sync_no * NCTA);

        // ---- phase B: LSTM cell + dual LN for batch j (skip once past length) ----
        if (t < g_len[j]) {
            float* shh = cellf;
            float* scc = cellf + Hh;
            float* red = cellf + 2 * Hh;   // 36 floats
            float ph = 0.f, ph2 = 0.f, pc = 0.f, pc2 = 0.f;
            const float* gb = g_gates + (size_t)j * Gg;
            float* cj = g_c + (size_t)j * Hh;
            for (int jj = tid; jj < Hh; jj += 256) {
                float ig = gb[jj], fg = gb[Hh + jj], gg = gb[2 * Hh + jj], og = gb[3 * Hh + jj];
                float cn = sigf(fg) * cj[jj] + sigf(ig) * tanhf(gg);
                float hr = sigf(og) * tanhf(cn);
                shh[jj] = hr; scc[jj] = cn;
                ph += hr; ph2 += hr * hr; pc += cn; pc2 += cn * cn;
            }
#pragma unroll
            for (int o = 16; o; o >>= 1) {
                ph  += __shfl_down_sync(0xffffffffu, ph, o);
                ph2 += __shfl_down_sync(0xffffffffu, ph2, o);
                pc  += __shfl_down_sync(0xffffffffu, pc, o);
                pc2 += __shfl_down_sync(0xffffffffu, pc2, o);
            }
            if (l == 0) { red[w * 4 + 0] = ph; red[w * 4 + 1] = ph2; red[w * 4 + 2] = pc; red[w * 4 + 3] = pc2; }
            __syncthreads();
            if (tid == 0) {
                float a0 = 0, a1 = 0, a2 = 0, a3 = 0;
                for (int i = 0; i < 8; i++) { a0 += red[4 * i]; a1 += red[4 * i + 1]; a2 += red[4 * i + 2]; a3 += red[4 * i + 3]; }
                red[32] = a0; red[33] = a1; red[34] = a2; red[35] = a3;
            }
            __syncthreads();
            const float inv = 1.0f / 768.0f;
            float muh = red[32] * inv, varh = red[33] * inv - muh * muh;
            float muc = red[34] * inv, varc = red[35] * inv - muc * muc;
            float rsh = rsqrtf(varh + 1e-5f), rsc = rsqrtf(varc + 1e-5f);
            bool last = (t == g_len[j] - 1);
            for (int jj = tid; jj < Hh; jj += 256) {
                float hv = (shh[jj] - muh) * rsh * gmh[jj] + bth[jj];
                float cv = (scc[jj] - muc) * rsc * gmc[jj] + btc[jj];
                g_hpk[(size_t)j * Hh + jj] = pksplit(hv);
                cj[jj] = cv;
                if (last) out[(size_t)j * Hh + jj] = hv;
            }
        }
        grid_sync(++sync_no * NCTA);
    }
}

// ---------------- host launcher (graph-capturable) ----------------
extern "C" void kernel_launch(void* const* d_in, const int* in_sizes, int n_in,
                              void* d_out, int out_size) {
    const int*   msg  = (const int*)d_in[0];
    const int*   mlen = (const int*)d_in[1];
    const float* embt = (const float*)d_in[2];
    const float* Wih  = (const float*)d_in[3];
    const float* Whh  = (const float*)d_in[4];
    const float* bih  = (const float*)d_in[5];
    const float* bhh  = (const float*)d_in[6];
    const float* gmh  = (const float*)d_in[7];
    const float* bth  = (const float*)d_in[8];
    const float* gmc  = (const float*)d_in[9];
    const float* btc  = (const float*)d_in[10];
    float* out = (float*)d_out;

    void* hp; cudaGetSymbolAddress(&hp, g_hpk);
    void* cp; cudaGetSymbolAddress(&cp, g_c);
    cudaMemsetAsync(hp, 0, Bb * Hh * sizeof(uint32_t));
    cudaMemsetAsync(cp, 0, Bb * Hh * sizeof(float));

    k0_setup<<<1, 256>>>(msg, mlen);
    k1_xproj<<<dim3(64, 48), 256>>>(embt, Wih, bih);

    size_t smem = (size_t)(48 * WPAD + 2 * 64 * HPAD) * sizeof(uint32_t);  // 183,040 B
    cudaFuncSetAttribute(krec, cudaFuncAttributeMaxDynamicSharedMemorySize, (int)smem);
    krec<<<NCTA, 256, smem>>>(Whh, bhh, gmh, bth, gmc, btc, out);
}

// round 11
// speedup vs baseline: 3.3178x; 1.0844x over previous
#include <cuda_runtime.h>
#include <cuda_bf16.h>
#include <math.h>
#include <stdint.h>

#define Bb 128
#define Tt 64
#define Ee 768
#define Hh 768
#define Gg 3072
#define NCTA 128
#define WPAD 772
#define HPAD 68

__device__ int      g_len[Bb];
__device__ int      g_nrows;
__device__ int      g_rows[Bb * Tt];
__device__ int      g_erow[Bb * Tt];
__device__ float    g_xproj[Tt * Bb * Gg];
__device__ uint32_t g_hpk[Bb * Hh];        // h packed: (lo_bf16<<16)|hi_bf16
__device__ float    g_c[Bb * Hh];
__device__ float    g_gates[Bb * Gg];
__device__ unsigned g_bar;

__device__ __forceinline__ uint32_t pksplit(float v) {
    __nv_bfloat16 h = __float2bfloat16(v);
    float r = v - __bfloat162float(h);
    __nv_bfloat16 l = __float2bfloat16(r);
    return ((uint32_t)__bfloat16_as_ushort(l) << 16) | (uint32_t)__bfloat16_as_ushort(h);
}
#define HIPAIR(u0, u1) __byte_perm((u0), (u1), 0x5410)
#define LOPAIR(u0, u1) __byte_perm((u0), (u1), 0x7632)

__device__ __forceinline__ void mma16(float* c, const uint32_t* a, const uint32_t* b) {
    asm volatile("mma.sync.aligned.m16n8k16.row.col.f32.bf16.bf16.f32 "
        "{%0,%1,%2,%3}, {%4,%5,%6,%7}, {%8,%9}, {%0,%1,%2,%3};"
        : "+f"(c[0]), "+f"(c[1]), "+f"(c[2]), "+f"(c[3])
        : "r"(a[0]), "r"(a[1]), "r"(a[2]), "r"(a[3]), "r"(b[0]), "r"(b[1]));
}
__device__ __forceinline__ void cpa16(void* sdst, const void* g) {
    uint32_t sa = (uint32_t)__cvta_generic_to_shared(sdst);
    asm volatile("cp.async.cg.shared.global [%0], [%1], 16;" :: "r"(sa), "l"(g));
}

// fused LSTM cell elementwise: 5 EX2 + 2 RCP, branch-free, exact to fp32 rounding
__device__ __forceinline__ void cellop(float ig, float fg, float gg, float og,
                                       float c, float& cn, float& hr) {
    ig = fminf(fmaxf(ig, -25.f), 25.f);
    fg = fminf(fmaxf(fg, -25.f), 25.f);
    og = fminf(fmaxf(og, -25.f), 25.f);
    gg = fminf(fmaxf(gg, -12.5f), 12.5f);
    float A  = 1.f + __expf(-ig);
    float F  = 1.f + __expf(-fg);
    float eg = __expf(2.f * gg);
    float AG = A * (eg + 1.f);
    cn = __fdividef(c * AG + F * (eg - 1.f), F * AG);
    float cc = fminf(fmaxf(cn, -12.5f), 12.5f);
    float e2 = __expf(2.f * cc);
    hr = __fdividef(e2 - 1.f, (1.f + __expf(-og)) * (e2 + 1.f));
}

// ---------------- K0 ----------------
__global__ void k0_setup(const int* __restrict__ msg, const int* __restrict__ mlen) {
    __shared__ int s_flag;
    __shared__ int s_nr;
    int tid = threadIdx.x;
    if (tid == 0) { s_flag = 0; s_nr = 0; g_bar = 0; }
    __syncthreads();
    int local = 0;
    for (int i = tid; i < (Bb * Tt) / 2; i += 256)
        if (msg[2 * i + 1] != 0) local = 1;
    if (local) atomicOr(&s_flag, 1);
    __syncthreads();
    int is64 = (s_flag == 0);
    if (tid < Bb) {
        int lb = is64 ? mlen[2 * tid] : mlen[tid];
        g_len[tid] = lb;
        for (int t = 0; t < lb; t++) {
            int r = atomicAdd(&s_nr, 1);
            g_rows[r] = (tid << 6) | t;
            int mi = tid * Tt + t;
            g_erow[r] = is64 ? msg[2 * mi] : msg[mi];
        }
    }
    __syncthreads();
    if (tid == 0) g_nrows = s_nr;
}

// ---------------- K1: input projection, bf16x3 (proven R5 version) ----------
__global__ __launch_bounds__(256) void k1_xproj(const float* __restrict__ embt,
                                                const float* __restrict__ Wih,
                                                const float* __restrict__ bih) {
    __shared__ uint32_t As[128][36];
    __shared__ uint32_t Bs[64][36];
    __shared__ int s_bt[128];
    __shared__ int s_eoff[128];
    int tid = threadIdx.x;
    int nrows = g_nrows;
    int r0 = blockIdx.x * 128;
    if (r0 >= nrows) return;
    int n0 = blockIdx.y * 64;
    if (tid < 128) {
        int r = r0 + tid;
        if (r < nrows) { s_bt[tid] = g_rows[r]; s_eoff[tid] = g_erow[r] * Ee; }
        else           { s_bt[tid] = -1;        s_eoff[tid] = 0; }
    }
    const float* W1 = Wih + (size_t)Gg * Ee;
    int l = tid & 31, w = tid >> 5;
    int wm = w >> 1, wn = w & 1;
    float acc[2][4][4];
#pragma unroll
    for (int i = 0; i < 2; i++)
#pragma unroll
        for (int jn = 0; jn < 4; jn++)
#pragma unroll
            for (int q = 0; q < 4; q++) acc[i][jn][q] = 0.0f;
    int arow = tid >> 1, ak = (tid & 1) * 16;
    int brow = tid >> 2, bk = (tid & 3) * 8;
    for (int kk = 0; kk < Ee; kk += 32) {
        __syncthreads();
        const float* ap = embt + s_eoff[arow] + kk + ak;
#pragma unroll
        for (int i = 0; i < 4; i++) {
            float4 v = *(const float4*)(ap + 4 * i);
            As[arow][ak + 4 * i + 0] = pksplit(v.x);
            As[arow][ak + 4 * i + 1] = pksplit(v.y);
            As[arow][ak + 4 * i + 2] = pksplit(v.z);
            As[arow][ak + 4 * i + 3] = pksplit(v.w);
        }
        const float* bp = W1 + (size_t)(n0 + brow) * Ee + kk + bk;
#pragma unroll
        for (int i = 0; i < 2; i++) {
            float4 v = *(const float4*)(bp + 4 * i);
            Bs[brow][bk + 4 * i + 0] = pksplit(v.x);
            Bs[brow][bk + 4 * i + 1] = pksplit(v.y);
            Bs[brow][bk + 4 * i + 2] = pksplit(v.z);
            Bs[brow][bk + 4 * i + 3] = pksplit(v.w);
        }
        __syncthreads();
#pragma unroll
        for (int k16 = 0; k16 < 2; k16++) {
            int kp = k16 * 16 + (l & 3) * 2;
            uint32_t ahi[2][4], alo[2][4];
#pragma unroll
            for (int mt = 0; mt < 2; mt++) {
                int mb = wm * 32 + mt * 16 + (l >> 2);
                uint2 p0 = *(const uint2*)&As[mb][kp];
                uint2 p1 = *(const uint2*)&As[mb + 8][kp];
                uint2 p2 = *(const uint2*)&As[mb][kp + 8];
                uint2 p3 = *(const uint2*)&As[mb + 8][kp + 8];
                ahi[mt][0] = HIPAIR(p0.x, p0.y); alo[mt][0] = LOPAIR(p0.x, p0.y);
                ahi[mt][1] = HIPAIR(p1.x, p1.y); alo[mt][1] = LOPAIR(p1.x, p1.y);
                ahi[mt][2] = HIPAIR(p2.x, p2.y); alo[mt][2] = LOPAIR(p2.x, p2.y);
                ahi[mt][3] = HIPAIR(p3.x, p3.y); alo[mt][3] = LOPAIR(p3.x, p3.y);
            }
            uint32_t bhi[4][2], blo[4][2];
#pragma unroll
            for (int nt = 0; nt < 4; nt++) {
                int nb = wn * 32 + nt * 8 + (l >> 2);
                uint2 q0 = *(const uint2*)&Bs[nb][kp];
                uint2 q1 = *(const uint2*)&Bs[nb][kp + 8];
                bhi[nt][0] = HIPAIR(q0.x, q0.y); blo[nt][0] = LOPAIR(q0.x, q0.y);
                bhi[nt][1] = HIPAIR(q1.x, q1.y); blo[nt][1] = LOPAIR(q1.x, q1.y);
            }
#pragma unroll
            for (int mt = 0; mt < 2; mt++)
#pragma unroll
                for (int nt = 0; nt < 4; nt++) {
                    mma16(acc[mt][nt], ahi[mt], bhi[nt]);
                    mma16(acc[mt][nt], ahi[mt], blo[nt]);
                    mma16(acc[mt][nt], alo[mt], bhi[nt]);
                }
        }
    }
#pragma unroll
    for (int mt = 0; mt < 2; mt++) {
        int rbase = wm * 32 + mt * 16 + (l >> 2);
#pragma unroll
        for (int nt = 0; nt < 4; nt++) {
            int nc = n0 + wn * 32 + nt * 8 + 2 * (l & 3);
            float2 bias = *(const float2*)(bih + Gg + nc);
            int meta = s_bt[rbase];
            if (meta >= 0) {
                int b_ = meta >> 6, t_ = meta & 63;
                float2 o; o.x = acc[mt][nt][0] + bias.x; o.y = acc[mt][nt][1] + bias.y;
                *(float2*)(g_xproj + ((size_t)(t_ * Bb) + b_) * Gg + nc) = o;
            }
            meta = s_bt[rbase + 8];
            if (meta >= 0) {
                int b_ = meta >> 6, t_ = meta & 63;
                float2 o; o.x = acc[mt][nt][2] + bias.x; o.y = acc[mt][nt][3] + bias.y;
                *(float2*)(g_xproj + ((size_t)(t_ * Bb) + b_) * Gg + nc) = o;
            }
        }
    }
}

// ---------------- persistent recurrence ----------------
// single global 128-CTA barrier — exact pattern proven in rounds 4/5
__device__ __forceinline__ void grid_sync(unsigned target) {
    __syncthreads();
    if (threadIdx.x == 0) {
        __threadfence();
        atomicAdd(&g_bar, 1u);
        while (*(volatile unsigned*)&g_bar < target) { __nanosleep(64); }
        __threadfence();
    }
    __syncthreads();
}

extern __shared__ uint32_t dsm[];

__global__ __launch_bounds__(256, 1) void krec(
        const float* __restrict__ Whh, const float* __restrict__ bhh,
        const float* __restrict__ gmh, const float* __restrict__ bth,
        const float* __restrict__ gmc, const float* __restrict__ btc,
        float* __restrict__ out) {
    uint32_t* w_sh = dsm;
    uint32_t* hs   = dsm + 48 * WPAD;
    float* cellf   = (float*)(dsm + 48 * WPAD);

    int tid = threadIdx.x;
    int bg = blockIdx.x >> 6;
    int shard = blockIdx.x & 63;
    int j = blockIdx.x;

    const float* W1 = Whh + (size_t)Gg * Hh + (size_t)shard * 48 * Hh;
    for (int i = tid; i < 48 * (Hh / 4); i += 256) {
        int n = i / (Hh / 4), kq = (i % (Hh / 4)) * 4;
        float4 v = *(const float4*)(W1 + (size_t)n * Hh + kq);
        uint32_t* d = &w_sh[n * WPAD + kq];
        d[0] = pksplit(v.x); d[1] = pksplit(v.y); d[2] = pksplit(v.z); d[3] = pksplit(v.w);
    }

    int l = tid & 31, w = tid >> 5;
    int wm = w >> 1, wn = w & 1;
    int srow = tid & 63, skq = (tid >> 6) * 16;
    const uint32_t* hsrc_base = g_hpk + (size_t)(bg * 64 + srow) * Hh + skq;
    uint32_t* sdst = hs + srow * HPAD + skq;

    int r_  = wm * 16 + (l >> 2);
    int b0_ = bg * 64 + r_;
    int b1_ = b0_ + 8;
    int len_j = g_len[j];
    unsigned sync_no = 0;
    float2 bias[3];
#pragma unroll
    for (int nt = 0; nt < 3; nt++)
        bias[nt] = *(const float2*)(bhh + Gg + shard * 48 + wn * 24 + nt * 8 + 2 * (l & 3));

    for (int t = 0; t < Tt; t++) {
        // prefetch xproj (independent of h) before the MMA mainloop
        float2 xp0[3], xp1[3];
#pragma unroll
        for (int nt = 0; nt < 3; nt++) {
            int nc = shard * 48 + wn * 24 + nt * 8 + 2 * (l & 3);
            xp0[nt] = *(const float2*)(g_xproj + ((size_t)(t * Bb) + b0_) * Gg + nc);
            xp1[nt] = *(const float2*)(g_xproj + ((size_t)(t * Bb) + b1_) * Gg + nc);
        }

        float acc[3][4];
#pragma unroll
        for (int i = 0; i < 3; i++)
#pragma unroll
            for (int q = 0; q < 4; q++) acc[i][q] = 0.0f;

        {
#pragma unroll
            for (int i = 0; i < 4; i++) cpa16(sdst + 4 * i, hsrc_base + 4 * i);
            asm volatile("cp.async.commit_group;");
        }
#pragma unroll 1
        for (int c = 0; c < 12; c++) {
            if (c < 11) {
                const uint32_t* src = hsrc_base + (c + 1) * 64;
                uint32_t* dst = sdst + ((c + 1) & 1) * (64 * HPAD);
#pragma unroll
                for (int i = 0; i < 4; i++) cpa16(dst + 4 * i, src + 4 * i);
                asm volatile("cp.async.commit_group;");
                asm volatile("cp.async.wait_group 1;");
            } else {
                asm volatile("cp.async.wait_group 0;");
            }
            __syncthreads();
            const uint32_t* hb = hs + (c & 1) * (64 * HPAD);
#pragma unroll
            for (int k16 = 0; k16 < 4; k16++) {
                int kp = k16 * 16 + (l & 3) * 2;
                uint32_t ahi[4], alo[4];
                {
                    int ar = wm * 16 + (l >> 2);
                    uint2 p0 = *(const uint2*)&hb[ar * HPAD + kp];
                    uint2 p1 = *(const uint2*)&hb[(ar + 8) * HPAD + kp];
                    uint2 p2 = *(const uint2*)&hb[ar * HPAD + kp + 8];
                    uint2 p3 = *(const uint2*)&hb[(ar + 8) * HPAD + kp + 8];
                    ahi[0] = HIPAIR(p0.x, p0.y); alo[0] = LOPAIR(p0.x, p0.y);
                    ahi[1] = HIPAIR(p1.x, p1.y); alo[1] = LOPAIR(p1.x, p1.y);
                    ahi[2] = HIPAIR(p2.x, p2.y); alo[2] = LOPAIR(p2.x, p2.y);
                    ahi[3] = HIPAIR(p3.x, p3.y); alo[3] = LOPAIR(p3.x, p3.y);
                }
                int kg = c * 64 + kp;
#pragma unroll
                for (int nt = 0; nt < 3; nt++) {
                    int nr = wn * 24 + nt * 8 + (l >> 2);
                    uint2 q0 = *(const uint2*)&w_sh[nr * WPAD + kg];
                    uint2 q1 = *(const uint2*)&w_sh[nr * WPAD + kg + 8];
                    uint32_t bhi[2], blo[2];
                    bhi[0] = HIPAIR(q0.x, q0.y); blo[0] = LOPAIR(q0.x, q0.y);
                    bhi[1] = HIPAIR(q1.x, q1.y); blo[1] = LOPAIR(q1.x, q1.y);
                    mma16(acc[nt], ahi, bhi);
                    mma16(acc[nt], ahi, blo);
                    mma16(acc[nt], alo, bhi);
                }
            }
            __syncthreads();
        }
        // epilogue: store-only (xproj+bias already in registers)
#pragma unroll
        for (int nt = 0; nt < 3; nt++) {
            int nc = shard * 48 + wn * 24 + nt * 8 + 2 * (l & 3);
            float2 o;
            o.x = acc[nt][0] + xp0[nt].x + bias[nt].x;
            o.y = acc[nt][1] + xp0[nt].y + bias[nt].y;
            *(float2*)(g_gates + (size_t)b0_ * Gg + nc) = o;
            o.x = acc[nt][2] + xp1[nt].x + bias[nt].x;
            o.y = acc[nt][3] + xp1[nt].y + bias[nt].y;
            *(float2*)(g_gates + (size_t)b1_ * Gg + nc) = o;
        }
        grid_sync(++sync_no * NCTA);

        // ---- phase B: fused LSTM cell + dual LN for batch j ----
        if (t < len_j) {
            float* shh = cellf;
            float* scc = cellf + Hh;
            float* red = cellf + 2 * Hh;
            const float* gb = g_gates + (size_t)j * Gg;
            float* cj = g_c + (size_t)j * Hh;
            float s0 = 0.f, s1 = 0.f, s2 = 0.f, s3 = 0.f;
            for (int p = tid; p < 384; p += 256) {
                int jj = 2 * p;
                float2 ig = *(const float2*)(gb + jj);
                float2 fg = *(const float2*)(gb + Hh + jj);
                float2 gg = *(const float2*)(gb + 2 * Hh + jj);
                float2 og = *(const float2*)(gb + 3 * Hh + jj);
                float2 cp = *(const float2*)(cj + jj);
                float cn0, hr0, cn1, hr1;
                cellop(ig.x, fg.x, gg.x, og.x, cp.x, cn0, hr0);
                cellop(ig.y, fg.y, gg.y, og.y, cp.y, cn1, hr1);
                shh[jj] = hr0; shh[jj + 1] = hr1;
                scc[jj] = cn0; scc[jj + 1] = cn1;
                s0 += hr0 + hr1; s1 += hr0 * hr0 + hr1 * hr1;
                s2 += cn0 + cn1; s3 += cn0 * cn0 + cn1 * cn1;
            }
#pragma unroll
            for (int o = 16; o; o >>= 1) {
                s0 += __shfl_down_sync(0xffffffffu, s0, o);
                s1 += __shfl_down_sync(0xffffffffu, s1, o);
                s2 += __shfl_down_sync(0xffffffffu, s2, o);
                s3 += __shfl_down_sync(0xffffffffu, s3, o);
            }
            if (l == 0) { red[w * 4 + 0] = s0; red[w * 4 + 1] = s1; red[w * 4 + 2] = s2; red[w * 4 + 3] = s3; }
            __syncthreads();
            if (tid == 0) {
                float a0 = 0, a1 = 0, a2 = 0, a3 = 0;
                for (int i = 0; i < 8; i++) { a0 += red[4 * i]; a1 += red[4 * i + 1]; a2 += red[4 * i + 2]; a3 += red[4 * i + 3]; }
                red[32] = a0; red[33] = a1; red[34] = a2; red[35] = a3;
            }
            __syncthreads();
            const float inv = 1.0f / 768.0f;
            float muh = red[32] * inv, varh = red[33] * inv - muh * muh;
            float muc = red[34] * inv, varc = red[35] * inv - muc * muc;
            float rsh = rsqrtf(varh + 1e-5f), rsc = rsqrtf(varc + 1e-5f);
            bool last = (t == len_j - 1);
            for (int jj = tid; jj < Hh; jj += 256) {
                float hv = (shh[jj] - muh) * rsh * gmh[jj] + bth[jj];
                float cv = (scc[jj] - muc) * rsc * gmc[jj] + btc[jj];
                g_hpk[(size_t)j * Hh + jj] = pksplit(hv);
                cj[jj] = cv;
                if (last) out[(size_t)j * Hh + jj] = hv;
            }
        }
        grid_sync(++sync_no * NCTA);
    }
}

// ---------------- host launcher ----------------
extern "C" void kernel_launch(void* const* d_in, const int* in_sizes, int n_in,
                              void* d_out, int out_size) {
    const int*   msg  = (const int*)d_in[0];
    const int*   mlen = (const int*)d_in[1];
    const float* embt = (const float*)d_in[2];
    const float* Wih  = (const float*)d_in[3];
    const float* Whh  = (const float*)d_in[4];
    const float* bih  = (const float*)d_in[5];
    const float* bhh  = (const float*)d_in[6];
    const float* gmh  = (const float*)d_in[7];
    const float* bth  = (const float*)d_in[8];
    const float* gmc  = (const float*)d_in[9];
    const float* btc  = (const float*)d_in[10];
    float* out = (float*)d_out;

    void* hp; cudaGetSymbolAddress(&hp, g_hpk);
    void* cp; cudaGetSymbolAddress(&cp, g_c);
    cudaMemsetAsync(hp, 0, Bb * Hh * sizeof(uint32_t));
    cudaMemsetAsync(cp, 0, Bb * Hh * sizeof(float));

    k0_setup<<<1, 256>>>(msg, mlen);
    k1_xproj<<<dim3(64, 48), 256>>>(embt, Wih, bih);

    size_t smem = (size_t)(48 * WPAD + 2 * 64 * HPAD) * sizeof(uint32_t);  // 183,040 B
    cudaFuncSetAttribute(krec, cudaFuncAttributeMaxDynamicSharedMemorySize, (int)smem);
    krec<<<NCTA, 256, smem>>>(Whh, bhh, gmh, bth, gmc, btc, out);
}